// round 10
// baseline (speedup 1.0000x reference)
#include <cuda_runtime.h>
#include <cuda_fp16.h>
#include <mma.h>
#include <math.h>
#include <stdint.h>

using namespace nvcuda;

#define NUM_HEADS 32
#define EMB 4096
#define HEAD_DIM 128
#define BATCH 2
#define SEQ 2048

// ---------------------------------------------------------------------------
// Scratch (no allocations allowed) — all fp16 activations
// ---------------------------------------------------------------------------
__device__ __half g_qkv16[(size_t)BATCH * SEQ * 3 * EMB];  // 100 MB
__device__ __half g_y16[(size_t)BATCH * SEQ * EMB];        // 33.5 MB
__device__ __half g_a16[(size_t)BATCH * SEQ * EMB];        // 33.5 MB (x fp16)
__device__ __half g_b16[(size_t)3 * EMB * EMB];            // 100 MB (weights fp16)

__device__ __forceinline__ uint32_t smem_u32(const void* p) {
    uint32_t a;
    asm("{ .reg .u64 t; cvta.to.shared.u64 t, %1; cvt.u32.u64 %0, t; }"
        : "=r"(a) : "l"(p));
    return a;
}

#define CP_ASYNC16(saddr, gptr) \
    asm volatile("cp.async.cg.shared.global [%0], [%1], 16;" \
        :: "r"(saddr), "l"(gptr))
#define CP_COMMIT() asm volatile("cp.async.commit_group;")
#define CP_WAIT1()  asm volatile("cp.async.wait_group 1;")
#define CP_WAIT0()  asm volatile("cp.async.wait_group 0;")

#define LDSM_X4(r0, r1, r2, r3, addr) \
    asm volatile("ldmatrix.sync.aligned.m8n8.x4.shared.b16 {%0,%1,%2,%3}, [%4];" \
        : "=r"(r0), "=r"(r1), "=r"(r2), "=r"(r3) : "r"(addr))
#define LDSM_X4_T(r0, r1, r2, r3, addr) \
    asm volatile("ldmatrix.sync.aligned.m8n8.x4.trans.shared.b16 {%0,%1,%2,%3}, [%4];" \
        : "=r"(r0), "=r"(r1), "=r"(r2), "=r"(r3) : "r"(addr))

// ---------------------------------------------------------------------------
// fp32 -> fp16 conversion, 8 elements per thread
// ---------------------------------------------------------------------------
__global__ void __launch_bounds__(256) cvt16_kernel(
    const float* __restrict__ in, __half* __restrict__ out)
{
    size_t i = ((size_t)blockIdx.x * 256 + threadIdx.x) * 8;
    float4 v0 = *(const float4*)(in + i);
    float4 v1 = *(const float4*)(in + i + 4);
    __half2 h[4];
    h[0] = __floats2half2_rn(v0.x, v0.y);
    h[1] = __floats2half2_rn(v0.z, v0.w);
    h[2] = __floats2half2_rn(v1.x, v1.y);
    h[3] = __floats2half2_rn(v1.z, v1.w);
    *(uint4*)(out + i) = *(uint4*)h;
}

// ---------------------------------------------------------------------------
// fp16 WMMA GEMM, cp.async 3-stage pipeline, 256 threads, 8 warps as 2(M)x4(N),
// warp tile 64x32. Block 128x128, K-step 64 (half the barrier count of BK=32).
// 2-D grid: blockIdx.x = N tile (A-band reuse across a wave), y = M tile.
// MODE 0: output fp16 with fused RoPE (cols < 2*EMB). MODE 1: fp32 plain.
// ---------------------------------------------------------------------------
#define BM 128
#define BN 128
#define BK 64
#define AST 72
#define BST 136
#define ATILE (BM * AST)      // 9216 halves
#define BTILE (BK * BST)      // 8704 halves
#define STG (ATILE + BTILE)   // 17920 halves per stage
#define NSTAGE 3
#define GEMM_SMEM (STG * NSTAGE * 2)   // 107520 bytes

template <int MODE>
__global__ void __launch_bounds__(256, 2) gemm_f16_kernel(
    const __half* __restrict__ A, const __half* __restrict__ B,
    void* __restrict__ Cv,
    const float* __restrict__ fcos, const float* __restrict__ fsin,
    int M, int N, int K)
{
    extern __shared__ __half hsm[];
    const uint32_t smb = smem_u32(hsm);

    const int tid = threadIdx.x;
    const int wid = tid >> 5;
    const int l = tid & 31;
    const int wM = wid >> 2;   // 0..1
    const int wN = wid & 3;    // 0..3
    const int bm = blockIdx.y * BM;
    const int bn = blockIdx.x * BN;

    wmma::fragment<wmma::accumulator, 16, 16, 16, float> cf[4][2];
#pragma unroll
    for (int i = 0; i < 4; i++)
#pragma unroll
        for (int j = 0; j < 2; j++)
            wmma::fill_fragment(cf[i][j], 0.0f);

    // A: 128 rows x 8 chunks (16B) = 1024 chunks; B: 64 rows x 16 chunks = 1024
    const int ar = tid >> 1, ac = tid & 1;    // + it*... below
    const int br = tid >> 4, bc = tid & 15;

    auto load_stage = [&](int s, int k0) {
        uint32_t abase = smb + (uint32_t)(s * STG) * 2;
        uint32_t bbase = abase + (uint32_t)ATILE * 2;
#pragma unroll
        for (int it = 0; it < 4; it++) {
            int aidx = tid + it * 256;
            int arow = aidx >> 3, acol = aidx & 7;
            CP_ASYNC16(abase + (uint32_t)(arow * AST + acol * 8) * 2,
                       A + (size_t)(bm + arow) * K + k0 + acol * 8);
            int bidx = tid + it * 256;
            int brow = bidx >> 4, bcol = bidx & 15;
            CP_ASYNC16(bbase + (uint32_t)(brow * BST + bcol * 8) * 2,
                       B + (size_t)(k0 + brow) * N + bn + bcol * 8);
        }
        CP_COMMIT();
    };

    load_stage(0, 0);
    load_stage(1, BK);

    int st = 0;
    for (int k0 = 0; k0 < K; k0 += BK) {
        CP_WAIT1();
        __syncthreads();
        const __half* As = hsm + st * STG;
        const __half* Bs = As + ATILE;
#pragma unroll
        for (int kk = 0; kk < BK; kk += 16) {
            wmma::fragment<wmma::matrix_a, 16, 16, 16, __half, wmma::row_major> af[4];
            wmma::fragment<wmma::matrix_b, 16, 16, 16, __half, wmma::row_major> bf[2];
#pragma unroll
            for (int i = 0; i < 4; i++)
                wmma::load_matrix_sync(af[i], &As[(wM * 64 + i * 16) * AST + kk], AST);
#pragma unroll
            for (int j = 0; j < 2; j++)
                wmma::load_matrix_sync(bf[j], &Bs[kk * BST + wN * 32 + j * 16], BST);
#pragma unroll
            for (int i = 0; i < 4; i++)
#pragma unroll
                for (int j = 0; j < 2; j++)
                    wmma::mma_sync(cf[i][j], af[i], bf[j], cf[i][j]);
        }
        int kn = k0 + 2 * BK;
        if (kn < K) load_stage(st == 0 ? 2 : st - 1, kn);  // (st+2)%3
        else        CP_COMMIT();   // empty group keeps one-group-per-iter invariant
        st = (st == 2) ? 0 : st + 1;
        __syncthreads();
    }
    CP_WAIT0();
    __syncthreads();

    if (MODE == 1) {
        float* C = (float*)Cv;
#pragma unroll
        for (int i = 0; i < 4; i++)
#pragma unroll
            for (int j = 0; j < 2; j++) {
                size_t row = (size_t)bm + wM * 64 + i * 16;
                size_t col = (size_t)bn + wN * 32 + j * 16;
                wmma::store_matrix_sync(C + row * N + col, cf[i][j], N, wmma::mem_row_major);
            }
    } else {
        // fp16 output + fused RoPE on q/k column bands
        __half* C = (__half*)Cv;
        float* stage = (float*)hsm + wid * 320;  // 16x20 fp32 per warp
        const bool doRope = (bn < 2 * EMB);
        const int row_l = l >> 1;
        const int ch = (l & 1) * 8;
#pragma unroll
        for (int i = 0; i < 4; i++)
#pragma unroll
            for (int j = 0; j < 2; j++) {
                wmma::store_matrix_sync(stage, cf[i][j], 20, wmma::mem_row_major);
                __syncwarp();
                const float* sp = stage + row_l * 20 + ch;
                int grow = bm + wM * 64 + i * 16 + row_l;
                int gcol = bn + wN * 32 + j * 16 + ch;
                __half hbuf[8];
                if (doRope) {
                    int sidx = grow & (SEQ - 1);
                    int d2b = (gcol & 127) >> 1;
#pragma unroll
                    for (int t = 0; t < 4; t++) {
                        float c = fcos[sidx * 64 + d2b + t];
                        float sn = fsin[sidx * 64 + d2b + t];
                        float xr = sp[2 * t], xi = sp[2 * t + 1];
                        hbuf[2 * t]     = __float2half(xr * c - xi * sn);
                        hbuf[2 * t + 1] = __float2half(xr * sn + xi * c);
                    }
                } else {
#pragma unroll
                    for (int t = 0; t < 8; t++)
                        hbuf[t] = __float2half(sp[t]);
                }
                *(uint4*)(C + (size_t)grow * N + gcol) = *(uint4*)hbuf;
                __syncwarp();
            }
    }
}

// ---------------------------------------------------------------------------
// Flash attention, fp16 mma.sync m16n8k16, causal, online softmax.
// cp.async double-buffered K/V; ldmatrix.x4 fragments; P in registers.
// ---------------------------------------------------------------------------
#define FBQ 128
#define FBK 64
#define QST 136
#define QS_HALVES (FBQ * QST)          // 17408
#define KV_HALVES (FBK * QST)          // 8704
#define KVSTG (2 * KV_HALVES)          // 17408 (k+v per buffer)
#define FLASH_SMEM ((QS_HALVES + 2 * KVSTG) * 2)   // 104448 bytes

__device__ __forceinline__ void mma_f16(float* d,
    uint32_t a0, uint32_t a1, uint32_t a2, uint32_t a3,
    uint32_t b0, uint32_t b1)
{
    asm volatile(
        "mma.sync.aligned.m16n8k16.row.col.f32.f16.f16.f32 "
        "{%0,%1,%2,%3},{%4,%5,%6,%7},{%8,%9},{%0,%1,%2,%3};\n"
        : "+f"(d[0]), "+f"(d[1]), "+f"(d[2]), "+f"(d[3])
        : "r"(a0), "r"(a1), "r"(a2), "r"(a3), "r"(b0), "r"(b1));
}

__device__ __forceinline__ uint32_t packh2(float x, float y) {
    __half2 h = __floats2half2_rn(x, y);
    return *(uint32_t*)&h;
}

__global__ void __launch_bounds__(256, 2) flash_f16_kernel(
    const __half* __restrict__ qkv, __half* __restrict__ y)
{
    extern __shared__ __half fsm[];
    __half* qs = fsm;                       // 128 x 136

    const int tid = threadIdx.x;
    const int w = tid >> 5;
    const int l = tid & 31;
    const int lq = l >> 2;
    const int lr = l & 3;
    const int qt = blockIdx.x;
    const int h = blockIdx.y;
    const int b = blockIdx.z;
    const int q0 = qt * FBQ;

    const size_t rs = 3 * EMB;
    const __half* qb  = qkv + (size_t)(b * SEQ + q0) * rs + h * HEAD_DIM;
    const __half* kb0 = qkv + (size_t)(b * SEQ) * rs + EMB + h * HEAD_DIM;
    const __half* vb0 = kb0 + EMB;

    const uint32_t fsmu = smem_u32(fsm);
    const uint32_t qsu = fsmu;
    const uint32_t ksu0 = fsmu + (uint32_t)QS_HALVES * 2;
    const uint32_t vsu0 = ksu0 + (uint32_t)KV_HALVES * 2;

    const uint32_t qbase = qsu + (uint32_t)(((w * 16 + (l & 15)) * QST + ((l >> 4) << 3)) * 2);
    const uint32_t kbase0 = ksu0 + (uint32_t)(((((l & 7) + ((l >> 4) << 3)) * QST) + (((l >> 3) & 1) << 3)) * 2);
    const uint32_t vbase0 = vsu0 + (uint32_t)((((l & 15) * QST) + ((l >> 4) << 3)) * 2);

    const int lrow = tid >> 4, lcol = tid & 15;   // K/V tile loading coords

    auto load_kv = [&](int buf, int kt) {
        const __half* kb = kb0 + (size_t)kt * FBK * rs;
        const __half* vb = vb0 + (size_t)kt * FBK * rs;
        uint32_t kdst = ksu0 + (uint32_t)(buf * KVSTG) * 2;
        uint32_t vdst = kdst + (uint32_t)KV_HALVES * 2;
#pragma unroll
        for (int i = 0; i < 4; i++) {
            int row = lrow + i * 16;
            uint32_t soff = (uint32_t)(row * QST + lcol * 8) * 2;
            CP_ASYNC16(kdst + soff, kb + (size_t)row * rs + lcol * 8);
            CP_ASYNC16(vdst + soff, vb + (size_t)row * rs + lcol * 8);
        }
        CP_COMMIT();
    };

    // stage Q (plain stores): 128 rows x 16 chunks of 8 halves
#pragma unroll
    for (int i = 0; i < 8; i++) {
        int idx = tid + i * 256;
        int row = idx >> 4, c = idx & 15;
        *(uint4*)&qs[row * QST + c * 8] = *(const uint4*)(qb + (size_t)row * rs + c * 8);
    }

    float d[16][4];
#pragma unroll
    for (int nt = 0; nt < 16; nt++)
#pragma unroll
        for (int c = 0; c < 4; c++)
            d[nt][c] = 0.0f;

    float m0 = -INFINITY, m1 = -INFINITY, l0 = 0.0f, l1 = 0.0f;
    const float sc = 0.08838834764831845f;  // 1/sqrt(128)
    const int ktmax = 2 * qt + 1;
    const int myrowmax = q0 + w * 16 + 15;
    const int arow = w * 16 + lq;

    load_kv(0, 0);

    for (int kt = 0; kt <= ktmax; kt++) {
        const int buf = kt & 1;
        if (kt < ktmax) { load_kv(buf ^ 1, kt + 1); CP_WAIT1(); }
        else           { CP_WAIT0(); }
        __syncthreads();   // K/V tile kt visible to all; Q staged (iter 0)

        const uint32_t kvoff = (uint32_t)(buf * KVSTG) * 2;
        const uint32_t kbase = kbase0 + kvoff;
        const uint32_t vbase = vbase0 + kvoff;

        const bool active = (kt * FBK <= myrowmax);
        if (active) {
            // ---- S = Q @ K^T ----
            float s[8][4];
#pragma unroll
            for (int nt = 0; nt < 8; nt++)
#pragma unroll
                for (int c = 0; c < 4; c++)
                    s[nt][c] = 0.0f;

#pragma unroll
            for (int k = 0; k < 8; k++) {
                uint32_t a0, a1, a2, a3;
                LDSM_X4(a0, a1, a2, a3, qbase + k * 32);
#pragma unroll
                for (int ntp = 0; ntp < 4; ntp++) {
                    uint32_t b0, b1, b2, b3;
                    LDSM_X4(b0, b1, b2, b3, kbase + (uint32_t)(ntp * 16 * QST * 2) + k * 32);
                    mma_f16(s[2 * ntp],     a0, a1, a2, a3, b0, b1);
                    mma_f16(s[2 * ntp + 1], a0, a1, a2, a3, b2, b3);
                }
            }

            // ---- scale + causal mask ----
            const bool domask = (kt >= 2 * qt);
#pragma unroll
            for (int nt = 0; nt < 8; nt++)
#pragma unroll
                for (int c = 0; c < 4; c++) {
                    float v = s[nt][c] * sc;
                    if (domask) {
                        int kg = kt * FBK + nt * 8 + 2 * lr + (c & 1);
                        int rg = q0 + arow + ((c >= 2) ? 8 : 0);
                        if (kg > rg) v = -INFINITY;
                    }
                    s[nt][c] = v;
                }

            // ---- online softmax (rows arow, arow+8) ----
            float mx0 = -INFINITY, mx1 = -INFINITY;
#pragma unroll
            for (int nt = 0; nt < 8; nt++) {
                mx0 = fmaxf(mx0, fmaxf(s[nt][0], s[nt][1]));
                mx1 = fmaxf(mx1, fmaxf(s[nt][2], s[nt][3]));
            }
            mx0 = fmaxf(mx0, __shfl_xor_sync(0xffffffffu, mx0, 1));
            mx0 = fmaxf(mx0, __shfl_xor_sync(0xffffffffu, mx0, 2));
            mx1 = fmaxf(mx1, __shfl_xor_sync(0xffffffffu, mx1, 1));
            mx1 = fmaxf(mx1, __shfl_xor_sync(0xffffffffu, mx1, 2));

            float nm0 = fmaxf(m0, mx0), nm1 = fmaxf(m1, mx1);
            float al0 = __expf(m0 - nm0), al1 = __expf(m1 - nm1);
            m0 = nm0; m1 = nm1;

            float sum0 = 0.0f, sum1 = 0.0f;
#pragma unroll
            for (int nt = 0; nt < 8; nt++) {
                float p0 = __expf(s[nt][0] - nm0);
                float p1 = __expf(s[nt][1] - nm0);
                float p2 = __expf(s[nt][2] - nm1);
                float p3 = __expf(s[nt][3] - nm1);
                s[nt][0] = p0; s[nt][1] = p1; s[nt][2] = p2; s[nt][3] = p3;
                sum0 += p0 + p1; sum1 += p2 + p3;
            }
            sum0 += __shfl_xor_sync(0xffffffffu, sum0, 1);
            sum0 += __shfl_xor_sync(0xffffffffu, sum0, 2);
            sum1 += __shfl_xor_sync(0xffffffffu, sum1, 1);
            sum1 += __shfl_xor_sync(0xffffffffu, sum1, 2);
            l0 = l0 * al0 + sum0;
            l1 = l1 * al1 + sum1;

#pragma unroll
            for (int nt = 0; nt < 16; nt++) {
                d[nt][0] *= al0; d[nt][1] *= al0;
                d[nt][2] *= al1; d[nt][3] *= al1;
            }

            // ---- O += P @ V (P fragments live in s[] registers) ----
#pragma unroll
            for (int kbk = 0; kbk < 4; kbk++) {
                uint32_t a0 = packh2(s[2 * kbk][0],     s[2 * kbk][1]);
                uint32_t a1 = packh2(s[2 * kbk][2],     s[2 * kbk][3]);
                uint32_t a2 = packh2(s[2 * kbk + 1][0], s[2 * kbk + 1][1]);
                uint32_t a3 = packh2(s[2 * kbk + 1][2], s[2 * kbk + 1][3]);
#pragma unroll
                for (int ntp = 0; ntp < 8; ntp++) {
                    uint32_t b0, b1, b2, b3;
                    LDSM_X4_T(b0, b1, b2, b3,
                              vbase + (uint32_t)(kbk * 16 * QST * 2) + ntp * 32);
                    mma_f16(d[2 * ntp],     a0, a1, a2, a3, b0, b1);
                    mma_f16(d[2 * ntp + 1], a0, a1, a2, a3, b2, b3);
                }
            }
        }
        __syncthreads();   // compute on buf done before next iter overwrites it
    }

    // epilogue: divide by l, write fp16 y
    float inv0 = 1.0f / l0, inv1 = 1.0f / l1;
    __half* yb  = y + (size_t)(b * SEQ + q0 + arow) * EMB + h * HEAD_DIM;
    __half* yb2 = yb + (size_t)8 * EMB;
#pragma unroll
    for (int nt = 0; nt < 16; nt++) {
        __half2 o0 = __floats2half2_rn(d[nt][0] * inv0, d[nt][1] * inv0);
        __half2 o1 = __floats2half2_rn(d[nt][2] * inv1, d[nt][3] * inv1);
        *(__half2*)&yb[nt * 8 + 2 * lr]  = o0;
        *(__half2*)&yb2[nt * 8 + 2 * lr] = o1;
    }
}

// ---------------------------------------------------------------------------
// Launch
// ---------------------------------------------------------------------------
extern "C" void kernel_launch(void* const* d_in, const int* in_sizes, int n_in,
                              void* d_out, int out_size)
{
    const float* x       = (const float*)d_in[0];
    const float* w_atten = (const float*)d_in[1];
    const float* w_proj  = (const float*)d_in[2];
    const float* fcos    = (const float*)d_in[3];
    const float* fsin    = (const float*)d_in[4];
    float* out = (float*)d_out;

    __half *qkv16 = nullptr, *y16 = nullptr, *a16 = nullptr, *b16 = nullptr;
    cudaGetSymbolAddress((void**)&qkv16, g_qkv16);
    cudaGetSymbolAddress((void**)&y16, g_y16);
    cudaGetSymbolAddress((void**)&a16, g_a16);
    cudaGetSymbolAddress((void**)&b16, g_b16);

    cudaFuncSetAttribute(gemm_f16_kernel<0>, cudaFuncAttributeMaxDynamicSharedMemorySize,
                         GEMM_SMEM);
    cudaFuncSetAttribute(gemm_f16_kernel<1>, cudaFuncAttributeMaxDynamicSharedMemorySize,
                         GEMM_SMEM);
    cudaFuncSetAttribute(flash_f16_kernel, cudaFuncAttributeMaxDynamicSharedMemorySize,
                         FLASH_SMEM);

    const int MROWS = BATCH * SEQ;                    // 4096
    const size_t NE = (size_t)MROWS * EMB;            // 16.7M
    const size_t NW1 = (size_t)EMB * 3 * EMB;         // 50.3M

    // 1) convert x and w_atten to fp16
    cvt16_kernel<<<(int)(NE / 2048), 256>>>(x, a16);
    cvt16_kernel<<<(int)(NW1 / 2048), 256>>>(w_atten, b16);

    // 2) qkv16 = rope(x @ w_atten) — fused epilogue
    {
        dim3 grid((3 * EMB) / BN, MROWS / BM);
        gemm_f16_kernel<0><<<grid, 256, GEMM_SMEM>>>(a16, b16, qkv16, fcos, fsin,
                                                     MROWS, 3 * EMB, EMB);
    }

    // 3) flash attention -> y16
    {
        dim3 grid(SEQ / FBQ, NUM_HEADS, BATCH);
        flash_f16_kernel<<<grid, 256, FLASH_SMEM>>>(qkv16, y16);
    }

    // 4) convert w_proj, then out = y @ w_proj (fp32 out)
    cvt16_kernel<<<(int)(NE / 2048), 256>>>(w_proj, b16);
    {
        dim3 grid(EMB / BN, MROWS / BM);
        gemm_f16_kernel<1><<<grid, 256, GEMM_SMEM>>>(y16, b16, out, nullptr, nullptr,
                                                     MROWS, EMB, EMB);
    }
}

// round 11
// speedup vs baseline: 1.0155x; 1.0155x over previous
#include <cuda_runtime.h>
#include <cuda_fp16.h>
#include <mma.h>
#include <math.h>
#include <stdint.h>

using namespace nvcuda;

#define NUM_HEADS 32
#define EMB 4096
#define HEAD_DIM 128
#define BATCH 2
#define SEQ 2048

// ---------------------------------------------------------------------------
// Scratch (no allocations allowed) — all fp16 activations
// ---------------------------------------------------------------------------
__device__ __half g_qkv16[(size_t)BATCH * SEQ * 3 * EMB];  // 100 MB
__device__ __half g_y16[(size_t)BATCH * SEQ * EMB];        // 33.5 MB
__device__ __half g_a16[(size_t)BATCH * SEQ * EMB];        // 33.5 MB (x fp16)
__device__ __half g_b16[(size_t)3 * EMB * EMB];            // 100 MB (weights fp16)

__device__ __forceinline__ uint32_t smem_u32(const void* p) {
    uint32_t a;
    asm("{ .reg .u64 t; cvta.to.shared.u64 t, %1; cvt.u32.u64 %0, t; }"
        : "=r"(a) : "l"(p));
    return a;
}

#define CP_ASYNC16(saddr, gptr) \
    asm volatile("cp.async.cg.shared.global [%0], [%1], 16;" \
        :: "r"(saddr), "l"(gptr))
#define CP_COMMIT() asm volatile("cp.async.commit_group;")
#define CP_WAIT2()  asm volatile("cp.async.wait_group 2;")
#define CP_WAIT1()  asm volatile("cp.async.wait_group 1;")
#define CP_WAIT0()  asm volatile("cp.async.wait_group 0;")

#define LDSM_X4(r0, r1, r2, r3, addr) \
    asm volatile("ldmatrix.sync.aligned.m8n8.x4.shared.b16 {%0,%1,%2,%3}, [%4];" \
        : "=r"(r0), "=r"(r1), "=r"(r2), "=r"(r3) : "r"(addr))
#define LDSM_X4_T(r0, r1, r2, r3, addr) \
    asm volatile("ldmatrix.sync.aligned.m8n8.x4.trans.shared.b16 {%0,%1,%2,%3}, [%4];" \
        : "=r"(r0), "=r"(r1), "=r"(r2), "=r"(r3) : "r"(addr))

// ---------------------------------------------------------------------------
// fp32 -> fp16 conversion, 8 elements per thread
// ---------------------------------------------------------------------------
__global__ void __launch_bounds__(256) cvt16_kernel(
    const float* __restrict__ in, __half* __restrict__ out)
{
    size_t i = ((size_t)blockIdx.x * 256 + threadIdx.x) * 8;
    float4 v0 = *(const float4*)(in + i);
    float4 v1 = *(const float4*)(in + i + 4);
    __half2 h[4];
    h[0] = __floats2half2_rn(v0.x, v0.y);
    h[1] = __floats2half2_rn(v0.z, v0.w);
    h[2] = __floats2half2_rn(v1.x, v1.y);
    h[3] = __floats2half2_rn(v1.z, v1.w);
    *(uint4*)(out + i) = *(uint4*)h;
}

// ---------------------------------------------------------------------------
// fp16 WMMA GEMM, cp.async 4-stage pipeline (wait_group 2 for deep slack),
// 256 threads, 8 warps as 2(M)x4(N), warp tile 64x32. Block 128x128, K-step 32.
// 2-D grid: blockIdx.x = N tile, y = M tile (natural A-band reuse in a wave).
// MODE 0: output fp16 with fused RoPE (cols < 2*EMB). MODE 1: fp32 plain.
// ---------------------------------------------------------------------------
#define BM 128
#define BN 128
#define BK 32
#define AST 40
#define BST 136
#define ATILE (BM * AST)      // 5120 halves
#define BTILE (BK * BST)      // 4352 halves
#define STG (ATILE + BTILE)   // 9472 halves per stage
#define NSTAGE 4
#define GEMM_SMEM (STG * NSTAGE * 2)   // 75776 bytes

template <int MODE>
__global__ void __launch_bounds__(256, 2) gemm_f16_kernel(
    const __half* __restrict__ A, const __half* __restrict__ B,
    void* __restrict__ Cv,
    const float* __restrict__ fcos, const float* __restrict__ fsin,
    int M, int N, int K)
{
    extern __shared__ __half hsm[];
    const uint32_t smb = smem_u32(hsm);

    const int tid = threadIdx.x;
    const int wid = tid >> 5;
    const int l = tid & 31;
    const int wM = wid >> 2;   // 0..1
    const int wN = wid & 3;    // 0..3
    const int bm = blockIdx.y * BM;
    const int bn = blockIdx.x * BN;

    wmma::fragment<wmma::accumulator, 16, 16, 16, float> cf[4][2];
#pragma unroll
    for (int i = 0; i < 4; i++)
#pragma unroll
        for (int j = 0; j < 2; j++)
            wmma::fill_fragment(cf[i][j], 0.0f);

    const int ar = tid >> 2, ac = tid & 3;    // A: rows ar, ar+64; chunk ac
    const int br = tid >> 4, bc = tid & 15;   // B: rows br, br+16; chunk bc

    auto load_stage = [&](int s, int k0) {
        uint32_t abase = smb + (uint32_t)(s * STG) * 2;
        uint32_t bbase = abase + (uint32_t)ATILE * 2;
#pragma unroll
        for (int it = 0; it < 2; it++) {
            CP_ASYNC16(abase + (uint32_t)((ar + it * 64) * AST + ac * 8) * 2,
                       A + (size_t)(bm + ar + it * 64) * K + k0 + ac * 8);
            CP_ASYNC16(bbase + (uint32_t)((br + it * 16) * BST + bc * 8) * 2,
                       B + (size_t)(k0 + br + it * 16) * N + bn + bc * 8);
        }
        CP_COMMIT();
    };

    load_stage(0, 0);
    load_stage(1, BK);
    load_stage(2, 2 * BK);

    int st = 0;
    for (int k0 = 0; k0 < K; k0 += BK) {
        CP_WAIT2();
        __syncthreads();
        const __half* As = hsm + st * STG;
        const __half* Bs = As + ATILE;
#pragma unroll
        for (int kk = 0; kk < BK; kk += 16) {
            wmma::fragment<wmma::matrix_a, 16, 16, 16, __half, wmma::row_major> af[4];
            wmma::fragment<wmma::matrix_b, 16, 16, 16, __half, wmma::row_major> bf[2];
#pragma unroll
            for (int i = 0; i < 4; i++)
                wmma::load_matrix_sync(af[i], &As[(wM * 64 + i * 16) * AST + kk], AST);
#pragma unroll
            for (int j = 0; j < 2; j++)
                wmma::load_matrix_sync(bf[j], &Bs[kk * BST + wN * 32 + j * 16], BST);
#pragma unroll
            for (int i = 0; i < 4; i++)
#pragma unroll
                for (int j = 0; j < 2; j++)
                    wmma::mma_sync(cf[i][j], af[i], bf[j], cf[i][j]);
        }
        int kn = k0 + 3 * BK;
        if (kn < K) load_stage((st + 3) & 3, kn);
        else        CP_COMMIT();   // empty group keeps one-group-per-iter invariant
        st = (st + 1) & 3;
        __syncthreads();
    }
    CP_WAIT0();
    __syncthreads();

    if (MODE == 1) {
        float* C = (float*)Cv;
#pragma unroll
        for (int i = 0; i < 4; i++)
#pragma unroll
            for (int j = 0; j < 2; j++) {
                size_t row = (size_t)bm + wM * 64 + i * 16;
                size_t col = (size_t)bn + wN * 32 + j * 16;
                wmma::store_matrix_sync(C + row * N + col, cf[i][j], N, wmma::mem_row_major);
            }
    } else {
        // fp16 output + fused RoPE on q/k column bands
        __half* C = (__half*)Cv;
        float* stage = (float*)hsm + wid * 320;  // 16x20 fp32 per warp
        const bool doRope = (bn < 2 * EMB);
        const int row_l = l >> 1;
        const int ch = (l & 1) * 8;
#pragma unroll
        for (int i = 0; i < 4; i++)
#pragma unroll
            for (int j = 0; j < 2; j++) {
                wmma::store_matrix_sync(stage, cf[i][j], 20, wmma::mem_row_major);
                __syncwarp();
                const float* sp = stage + row_l * 20 + ch;
                int grow = bm + wM * 64 + i * 16 + row_l;
                int gcol = bn + wN * 32 + j * 16 + ch;
                __half hbuf[8];
                if (doRope) {
                    int sidx = grow & (SEQ - 1);
                    int d2b = (gcol & 127) >> 1;
#pragma unroll
                    for (int t = 0; t < 4; t++) {
                        float c = fcos[sidx * 64 + d2b + t];
                        float sn = fsin[sidx * 64 + d2b + t];
                        float xr = sp[2 * t], xi = sp[2 * t + 1];
                        hbuf[2 * t]     = __float2half(xr * c - xi * sn);
                        hbuf[2 * t + 1] = __float2half(xr * sn + xi * c);
                    }
                } else {
#pragma unroll
                    for (int t = 0; t < 8; t++)
                        hbuf[t] = __float2half(sp[t]);
                }
                *(uint4*)(C + (size_t)grow * N + gcol) = *(uint4*)hbuf;
                __syncwarp();
            }
    }
}

// ---------------------------------------------------------------------------
// Flash attention, fp16 mma.sync m16n8k16, causal, online softmax.
// cp.async double-buffered K/V; ldmatrix.x4 fragments; P in registers.
// Heavy q-tiles scheduled first (reversed blockIdx.x) to kill wave-tail.
// ---------------------------------------------------------------------------
#define FBQ 128
#define FBK 64
#define QST 136
#define QS_HALVES (FBQ * QST)          // 17408
#define KV_HALVES (FBK * QST)          // 8704
#define KVSTG (2 * KV_HALVES)          // 17408 (k+v per buffer)
#define FLASH_SMEM ((QS_HALVES + 2 * KVSTG) * 2)   // 104448 bytes

__device__ __forceinline__ void mma_f16(float* d,
    uint32_t a0, uint32_t a1, uint32_t a2, uint32_t a3,
    uint32_t b0, uint32_t b1)
{
    asm volatile(
        "mma.sync.aligned.m16n8k16.row.col.f32.f16.f16.f32 "
        "{%0,%1,%2,%3},{%4,%5,%6,%7},{%8,%9},{%0,%1,%2,%3};\n"
        : "+f"(d[0]), "+f"(d[1]), "+f"(d[2]), "+f"(d[3])
        : "r"(a0), "r"(a1), "r"(a2), "r"(a3), "r"(b0), "r"(b1));
}

__device__ __forceinline__ uint32_t packh2(float x, float y) {
    __half2 h = __floats2half2_rn(x, y);
    return *(uint32_t*)&h;
}

__global__ void __launch_bounds__(256, 2) flash_f16_kernel(
    const __half* __restrict__ qkv, __half* __restrict__ y)
{
    extern __shared__ __half fsm[];
    __half* qs = fsm;                       // 128 x 136

    const int tid = threadIdx.x;
    const int w = tid >> 5;
    const int l = tid & 31;
    const int lq = l >> 2;
    const int lr = l & 3;
    const int qt = gridDim.x - 1 - blockIdx.x;   // heavy tiles first
    const int h = blockIdx.y;
    const int b = blockIdx.z;
    const int q0 = qt * FBQ;

    const size_t rs = 3 * EMB;
    const __half* qb  = qkv + (size_t)(b * SEQ + q0) * rs + h * HEAD_DIM;
    const __half* kb0 = qkv + (size_t)(b * SEQ) * rs + EMB + h * HEAD_DIM;
    const __half* vb0 = kb0 + EMB;

    const uint32_t fsmu = smem_u32(fsm);
    const uint32_t qsu = fsmu;
    const uint32_t ksu0 = fsmu + (uint32_t)QS_HALVES * 2;
    const uint32_t vsu0 = ksu0 + (uint32_t)KV_HALVES * 2;

    const uint32_t qbase = qsu + (uint32_t)(((w * 16 + (l & 15)) * QST + ((l >> 4) << 3)) * 2);
    const uint32_t kbase0 = ksu0 + (uint32_t)(((((l & 7) + ((l >> 4) << 3)) * QST) + (((l >> 3) & 1) << 3)) * 2);
    const uint32_t vbase0 = vsu0 + (uint32_t)((((l & 15) * QST) + ((l >> 4) << 3)) * 2);

    const int lrow = tid >> 4, lcol = tid & 15;   // K/V tile loading coords

    auto load_kv = [&](int buf, int kt) {
        const __half* kb = kb0 + (size_t)kt * FBK * rs;
        const __half* vb = vb0 + (size_t)kt * FBK * rs;
        uint32_t kdst = ksu0 + (uint32_t)(buf * KVSTG) * 2;
        uint32_t vdst = kdst + (uint32_t)KV_HALVES * 2;
#pragma unroll
        for (int i = 0; i < 4; i++) {
            int row = lrow + i * 16;
            uint32_t soff = (uint32_t)(row * QST + lcol * 8) * 2;
            CP_ASYNC16(kdst + soff, kb + (size_t)row * rs + lcol * 8);
            CP_ASYNC16(vdst + soff, vb + (size_t)row * rs + lcol * 8);
        }
        CP_COMMIT();
    };

    // stage Q (plain stores): 128 rows x 16 chunks of 8 halves
#pragma unroll
    for (int i = 0; i < 8; i++) {
        int idx = tid + i * 256;
        int row = idx >> 4, c = idx & 15;
        *(uint4*)&qs[row * QST + c * 8] = *(const uint4*)(qb + (size_t)row * rs + c * 8);
    }

    float d[16][4];
#pragma unroll
    for (int nt = 0; nt < 16; nt++)
#pragma unroll
        for (int c = 0; c < 4; c++)
            d[nt][c] = 0.0f;

    float m0 = -INFINITY, m1 = -INFINITY, l0 = 0.0f, l1 = 0.0f;
    const float sc = 0.08838834764831845f;  // 1/sqrt(128)
    const int ktmax = 2 * qt + 1;
    const int myrowmax = q0 + w * 16 + 15;
    const int arow = w * 16 + lq;

    load_kv(0, 0);

    for (int kt = 0; kt <= ktmax; kt++) {
        const int buf = kt & 1;
        if (kt < ktmax) { load_kv(buf ^ 1, kt + 1); CP_WAIT1(); }
        else           { CP_WAIT0(); }
        __syncthreads();   // K/V tile kt visible to all; Q staged (iter 0)

        const uint32_t kvoff = (uint32_t)(buf * KVSTG) * 2;
        const uint32_t kbase = kbase0 + kvoff;
        const uint32_t vbase = vbase0 + kvoff;

        const bool active = (kt * FBK <= myrowmax);
        if (active) {
            // ---- S = Q @ K^T ----
            float s[8][4];
#pragma unroll
            for (int nt = 0; nt < 8; nt++)
#pragma unroll
                for (int c = 0; c < 4; c++)
                    s[nt][c] = 0.0f;

#pragma unroll
            for (int k = 0; k < 8; k++) {
                uint32_t a0, a1, a2, a3;
                LDSM_X4(a0, a1, a2, a3, qbase + k * 32);
#pragma unroll
                for (int ntp = 0; ntp < 4; ntp++) {
                    uint32_t b0, b1, b2, b3;
                    LDSM_X4(b0, b1, b2, b3, kbase + (uint32_t)(ntp * 16 * QST * 2) + k * 32);
                    mma_f16(s[2 * ntp],     a0, a1, a2, a3, b0, b1);
                    mma_f16(s[2 * ntp + 1], a0, a1, a2, a3, b2, b3);
                }
            }

            // ---- scale + causal mask ----
            const bool domask = (kt >= 2 * qt);
#pragma unroll
            for (int nt = 0; nt < 8; nt++)
#pragma unroll
                for (int c = 0; c < 4; c++) {
                    float v = s[nt][c] * sc;
                    if (domask) {
                        int kg = kt * FBK + nt * 8 + 2 * lr + (c & 1);
                        int rg = q0 + arow + ((c >= 2) ? 8 : 0);
                        if (kg > rg) v = -INFINITY;
                    }
                    s[nt][c] = v;
                }

            // ---- online softmax (rows arow, arow+8) ----
            float mx0 = -INFINITY, mx1 = -INFINITY;
#pragma unroll
            for (int nt = 0; nt < 8; nt++) {
                mx0 = fmaxf(mx0, fmaxf(s[nt][0], s[nt][1]));
                mx1 = fmaxf(mx1, fmaxf(s[nt][2], s[nt][3]));
            }
            mx0 = fmaxf(mx0, __shfl_xor_sync(0xffffffffu, mx0, 1));
            mx0 = fmaxf(mx0, __shfl_xor_sync(0xffffffffu, mx0, 2));
            mx1 = fmaxf(mx1, __shfl_xor_sync(0xffffffffu, mx1, 1));
            mx1 = fmaxf(mx1, __shfl_xor_sync(0xffffffffu, mx1, 2));

            float nm0 = fmaxf(m0, mx0), nm1 = fmaxf(m1, mx1);
            float al0 = __expf(m0 - nm0), al1 = __expf(m1 - nm1);
            m0 = nm0; m1 = nm1;

            float sum0 = 0.0f, sum1 = 0.0f;
#pragma unroll
            for (int nt = 0; nt < 8; nt++) {
                float p0 = __expf(s[nt][0] - nm0);
                float p1 = __expf(s[nt][1] - nm0);
                float p2 = __expf(s[nt][2] - nm1);
                float p3 = __expf(s[nt][3] - nm1);
                s[nt][0] = p0; s[nt][1] = p1; s[nt][2] = p2; s[nt][3] = p3;
                sum0 += p0 + p1; sum1 += p2 + p3;
            }
            sum0 += __shfl_xor_sync(0xffffffffu, sum0, 1);
            sum0 += __shfl_xor_sync(0xffffffffu, sum0, 2);
            sum1 += __shfl_xor_sync(0xffffffffu, sum1, 1);
            sum1 += __shfl_xor_sync(0xffffffffu, sum1, 2);
            l0 = l0 * al0 + sum0;
            l1 = l1 * al1 + sum1;

#pragma unroll
            for (int nt = 0; nt < 16; nt++) {
                d[nt][0] *= al0; d[nt][1] *= al0;
                d[nt][2] *= al1; d[nt][3] *= al1;
            }

            // ---- O += P @ V (P fragments live in s[] registers) ----
#pragma unroll
            for (int kbk = 0; kbk < 4; kbk++) {
                uint32_t a0 = packh2(s[2 * kbk][0],     s[2 * kbk][1]);
                uint32_t a1 = packh2(s[2 * kbk][2],     s[2 * kbk][3]);
                uint32_t a2 = packh2(s[2 * kbk + 1][0], s[2 * kbk + 1][1]);
                uint32_t a3 = packh2(s[2 * kbk + 1][2], s[2 * kbk + 1][3]);
#pragma unroll
                for (int ntp = 0; ntp < 8; ntp++) {
                    uint32_t b0, b1, b2, b3;
                    LDSM_X4_T(b0, b1, b2, b3,
                              vbase + (uint32_t)(kbk * 16 * QST * 2) + ntp * 32);
                    mma_f16(d[2 * ntp],     a0, a1, a2, a3, b0, b1);
                    mma_f16(d[2 * ntp + 1], a0, a1, a2, a3, b2, b3);
                }
            }
        }
        __syncthreads();   // compute on buf done before next iter overwrites it
    }

    // epilogue: divide by l, write fp16 y
    float inv0 = 1.0f / l0, inv1 = 1.0f / l1;
    __half* yb  = y + (size_t)(b * SEQ + q0 + arow) * EMB + h * HEAD_DIM;
    __half* yb2 = yb + (size_t)8 * EMB;
#pragma unroll
    for (int nt = 0; nt < 16; nt++) {
        __half2 o0 = __floats2half2_rn(d[nt][0] * inv0, d[nt][1] * inv0);
        __half2 o1 = __floats2half2_rn(d[nt][2] * inv1, d[nt][3] * inv1);
        *(__half2*)&yb[nt * 8 + 2 * lr]  = o0;
        *(__half2*)&yb2[nt * 8 + 2 * lr] = o1;
    }
}

// ---------------------------------------------------------------------------
// Launch
// ---------------------------------------------------------------------------
extern "C" void kernel_launch(void* const* d_in, const int* in_sizes, int n_in,
                              void* d_out, int out_size)
{
    const float* x       = (const float*)d_in[0];
    const float* w_atten = (const float*)d_in[1];
    const float* w_proj  = (const float*)d_in[2];
    const float* fcos    = (const float*)d_in[3];
    const float* fsin    = (const float*)d_in[4];
    float* out = (float*)d_out;

    __half *qkv16 = nullptr, *y16 = nullptr, *a16 = nullptr, *b16 = nullptr;
    cudaGetSymbolAddress((void**)&qkv16, g_qkv16);
    cudaGetSymbolAddress((void**)&y16, g_y16);
    cudaGetSymbolAddress((void**)&a16, g_a16);
    cudaGetSymbolAddress((void**)&b16, g_b16);

    cudaFuncSetAttribute(gemm_f16_kernel<0>, cudaFuncAttributeMaxDynamicSharedMemorySize,
                         GEMM_SMEM);
    cudaFuncSetAttribute(gemm_f16_kernel<1>, cudaFuncAttributeMaxDynamicSharedMemorySize,
                         GEMM_SMEM);
    cudaFuncSetAttribute(flash_f16_kernel, cudaFuncAttributeMaxDynamicSharedMemorySize,
                         FLASH_SMEM);

    const int MROWS = BATCH * SEQ;                    // 4096
    const size_t NE = (size_t)MROWS * EMB;            // 16.7M
    const size_t NW1 = (size_t)EMB * 3 * EMB;         // 50.3M

    // 1) convert x and w_atten to fp16
    cvt16_kernel<<<(int)(NE / 2048), 256>>>(x, a16);
    cvt16_kernel<<<(int)(NW1 / 2048), 256>>>(w_atten, b16);

    // 2) qkv16 = rope(x @ w_atten) — fused epilogue
    {
        dim3 grid((3 * EMB) / BN, MROWS / BM);
        gemm_f16_kernel<0><<<grid, 256, GEMM_SMEM>>>(a16, b16, qkv16, fcos, fsin,
                                                     MROWS, 3 * EMB, EMB);
    }

    // 3) flash attention -> y16 (heavy tiles first)
    {
        dim3 grid(SEQ / FBQ, NUM_HEADS, BATCH);
        flash_f16_kernel<<<grid, 256, FLASH_SMEM>>>(qkv16, y16);
    }

    // 4) convert w_proj, then out = y @ w_proj (fp32 out)
    cvt16_kernel<<<(int)(NE / 2048), 256>>>(w_proj, b16);
    {
        dim3 grid(EMB / BN, MROWS / BM);
        gemm_f16_kernel<1><<<grid, 256, GEMM_SMEM>>>(y16, b16, out, nullptr, nullptr,
                                                     MROWS, EMB, EMB);
    }
}

// round 12
// speedup vs baseline: 1.0295x; 1.0137x over previous
#include <cuda_runtime.h>
#include <cuda_fp16.h>
#include <mma.h>
#include <math.h>
#include <stdint.h>

using namespace nvcuda;

#define NUM_HEADS 32
#define EMB 4096
#define HEAD_DIM 128
#define BATCH 2
#define SEQ 2048

// ---------------------------------------------------------------------------
// Scratch (no allocations allowed) — all fp16 activations
// ---------------------------------------------------------------------------
__device__ __half g_qkv16[(size_t)BATCH * SEQ * 3 * EMB];  // 100 MB
__device__ __half g_y16[(size_t)BATCH * SEQ * EMB];        // 33.5 MB
__device__ __half g_a16[(size_t)BATCH * SEQ * EMB];        // 33.5 MB (x fp16)
__device__ __half g_b16[(size_t)3 * EMB * EMB];            // 100 MB (weights fp16)

__device__ __forceinline__ uint32_t smem_u32(const void* p) {
    uint32_t a;
    asm("{ .reg .u64 t; cvta.to.shared.u64 t, %1; cvt.u32.u64 %0, t; }"
        : "=r"(a) : "l"(p));
    return a;
}

#define CP_ASYNC16(saddr, gptr) \
    asm volatile("cp.async.cg.shared.global [%0], [%1], 16;" \
        :: "r"(saddr), "l"(gptr))
#define CP_COMMIT() asm volatile("cp.async.commit_group;")
#define CP_WAIT1()  asm volatile("cp.async.wait_group 1;")
#define CP_WAIT0()  asm volatile("cp.async.wait_group 0;")

#define LDSM_X4(r0, r1, r2, r3, addr) \
    asm volatile("ldmatrix.sync.aligned.m8n8.x4.shared.b16 {%0,%1,%2,%3}, [%4];" \
        : "=r"(r0), "=r"(r1), "=r"(r2), "=r"(r3) : "r"(addr))
#define LDSM_X4_T(r0, r1, r2, r3, addr) \
    asm volatile("ldmatrix.sync.aligned.m8n8.x4.trans.shared.b16 {%0,%1,%2,%3}, [%4];" \
        : "=r"(r0), "=r"(r1), "=r"(r2), "=r"(r3) : "r"(addr))

// ---------------------------------------------------------------------------
// fp32 -> fp16 conversion, 8 elements per thread
// ---------------------------------------------------------------------------
__global__ void __launch_bounds__(256) cvt16_kernel(
    const float* __restrict__ in, __half* __restrict__ out)
{
    size_t i = ((size_t)blockIdx.x * 256 + threadIdx.x) * 8;
    float4 v0 = *(const float4*)(in + i);
    float4 v1 = *(const float4*)(in + i + 4);
    __half2 h[4];
    h[0] = __floats2half2_rn(v0.x, v0.y);
    h[1] = __floats2half2_rn(v0.z, v0.w);
    h[2] = __floats2half2_rn(v1.x, v1.y);
    h[3] = __floats2half2_rn(v1.z, v1.w);
    *(uint4*)(out + i) = *(uint4*)h;
}

// ---------------------------------------------------------------------------
// fp16 WMMA GEMM — exact R6 config (measured best): cp.async 3-stage pipeline,
// 256 threads, 8 warps as 2(M)x4(N), warp tile 64x32. Block 128x128, K-step 32.
// 2-D grid: blockIdx.x = N tile, y = M tile.
// MODE 0: output fp16 with fused RoPE (cols < 2*EMB). MODE 1: fp32 plain.
// ---------------------------------------------------------------------------
#define BM 128
#define BN 128
#define BK 32
#define AST 40
#define BST 136
#define ATILE (BM * AST)      // 5120 halves
#define BTILE (BK * BST)      // 4352 halves
#define STG (ATILE + BTILE)   // 9472 halves per stage
#define NSTAGE 3
#define GEMM_SMEM (STG * NSTAGE * 2)   // 56832 bytes

template <int MODE>
__global__ void __launch_bounds__(256, 2) gemm_f16_kernel(
    const __half* __restrict__ A, const __half* __restrict__ B,
    void* __restrict__ Cv,
    const float* __restrict__ fcos, const float* __restrict__ fsin,
    int M, int N, int K)
{
    extern __shared__ __half hsm[];
    const uint32_t smb = smem_u32(hsm);

    const int tid = threadIdx.x;
    const int wid = tid >> 5;
    const int l = tid & 31;
    const int wM = wid >> 2;   // 0..1
    const int wN = wid & 3;    // 0..3
    const int bm = blockIdx.y * BM;
    const int bn = blockIdx.x * BN;

    wmma::fragment<wmma::accumulator, 16, 16, 16, float> cf[4][2];
#pragma unroll
    for (int i = 0; i < 4; i++)
#pragma unroll
        for (int j = 0; j < 2; j++)
            wmma::fill_fragment(cf[i][j], 0.0f);

    const int ar = tid >> 2, ac = tid & 3;    // A: rows ar, ar+64; chunk ac
    const int br = tid >> 4, bc = tid & 15;   // B: rows br, br+16; chunk bc

    auto load_stage = [&](int s, int k0) {
        uint32_t abase = smb + (uint32_t)(s * STG) * 2;
        uint32_t bbase = abase + (uint32_t)ATILE * 2;
#pragma unroll
        for (int it = 0; it < 2; it++) {
            CP_ASYNC16(abase + (uint32_t)((ar + it * 64) * AST + ac * 8) * 2,
                       A + (size_t)(bm + ar + it * 64) * K + k0 + ac * 8);
            CP_ASYNC16(bbase + (uint32_t)((br + it * 16) * BST + bc * 8) * 2,
                       B + (size_t)(k0 + br + it * 16) * N + bn + bc * 8);
        }
        CP_COMMIT();
    };

    load_stage(0, 0);
    load_stage(1, BK);

    int st = 0;
    for (int k0 = 0; k0 < K; k0 += BK) {
        CP_WAIT1();
        __syncthreads();
        const __half* As = hsm + st * STG;
        const __half* Bs = As + ATILE;
#pragma unroll
        for (int kk = 0; kk < BK; kk += 16) {
            wmma::fragment<wmma::matrix_a, 16, 16, 16, __half, wmma::row_major> af[4];
            wmma::fragment<wmma::matrix_b, 16, 16, 16, __half, wmma::row_major> bf[2];
#pragma unroll
            for (int i = 0; i < 4; i++)
                wmma::load_matrix_sync(af[i], &As[(wM * 64 + i * 16) * AST + kk], AST);
#pragma unroll
            for (int j = 0; j < 2; j++)
                wmma::load_matrix_sync(bf[j], &Bs[kk * BST + wN * 32 + j * 16], BST);
#pragma unroll
            for (int i = 0; i < 4; i++)
#pragma unroll
                for (int j = 0; j < 2; j++)
                    wmma::mma_sync(cf[i][j], af[i], bf[j], cf[i][j]);
        }
        int kn = k0 + 2 * BK;
        if (kn < K) load_stage(st == 0 ? 2 : st - 1, kn);  // (st+2)%3
        else        CP_COMMIT();   // empty group keeps one-group-per-iter invariant
        st = (st == 2) ? 0 : st + 1;
        __syncthreads();
    }
    CP_WAIT0();
    __syncthreads();

    if (MODE == 1) {
        float* C = (float*)Cv;
#pragma unroll
        for (int i = 0; i < 4; i++)
#pragma unroll
            for (int j = 0; j < 2; j++) {
                size_t row = (size_t)bm + wM * 64 + i * 16;
                size_t col = (size_t)bn + wN * 32 + j * 16;
                wmma::store_matrix_sync(C + row * N + col, cf[i][j], N, wmma::mem_row_major);
            }
    } else {
        // fp16 output + fused RoPE on q/k column bands
        __half* C = (__half*)Cv;
        float* stage = (float*)hsm + wid * 320;  // 16x20 fp32 per warp
        const bool doRope = (bn < 2 * EMB);
        const int row_l = l >> 1;
        const int ch = (l & 1) * 8;
#pragma unroll
        for (int i = 0; i < 4; i++)
#pragma unroll
            for (int j = 0; j < 2; j++) {
                wmma::store_matrix_sync(stage, cf[i][j], 20, wmma::mem_row_major);
                __syncwarp();
                const float* sp = stage + row_l * 20 + ch;
                int grow = bm + wM * 64 + i * 16 + row_l;
                int gcol = bn + wN * 32 + j * 16 + ch;
                __half hbuf[8];
                if (doRope) {
                    int sidx = grow & (SEQ - 1);
                    int d2b = (gcol & 127) >> 1;
#pragma unroll
                    for (int t = 0; t < 4; t++) {
                        float c = fcos[sidx * 64 + d2b + t];
                        float sn = fsin[sidx * 64 + d2b + t];
                        float xr = sp[2 * t], xi = sp[2 * t + 1];
                        hbuf[2 * t]     = __float2half(xr * c - xi * sn);
                        hbuf[2 * t + 1] = __float2half(xr * sn + xi * c);
                    }
                } else {
#pragma unroll
                    for (int t = 0; t < 8; t++)
                        hbuf[t] = __float2half(sp[t]);
                }
                *(uint4*)(C + (size_t)grow * N + gcol) = *(uint4*)hbuf;
                __syncwarp();
            }
    }
}

// ---------------------------------------------------------------------------
// Flash attention, fp16 mma.sync m16n8k16, causal, online softmax.
// cp.async double-buffered K/V with ONE barrier per iteration:
//   wait0 -> sync (publishes tile kt AND retires compute on the buffer about
//   to be overwritten) -> issue load kt+1 -> compute kt.
// ldmatrix.x4 fragments; P in registers. Heavy q-tiles scheduled first.
// ---------------------------------------------------------------------------
#define FBQ 128
#define FBK 64
#define QST 136
#define QS_HALVES (FBQ * QST)          // 17408
#define KV_HALVES (FBK * QST)          // 8704
#define KVSTG (2 * KV_HALVES)          // 17408 (k+v per buffer)
#define FLASH_SMEM ((QS_HALVES + 2 * KVSTG) * 2)   // 104448 bytes

__device__ __forceinline__ void mma_f16(float* d,
    uint32_t a0, uint32_t a1, uint32_t a2, uint32_t a3,
    uint32_t b0, uint32_t b1)
{
    asm volatile(
        "mma.sync.aligned.m16n8k16.row.col.f32.f16.f16.f32 "
        "{%0,%1,%2,%3},{%4,%5,%6,%7},{%8,%9},{%0,%1,%2,%3};\n"
        : "+f"(d[0]), "+f"(d[1]), "+f"(d[2]), "+f"(d[3])
        : "r"(a0), "r"(a1), "r"(a2), "r"(a3), "r"(b0), "r"(b1));
}

__device__ __forceinline__ uint32_t packh2(float x, float y) {
    __half2 h = __floats2half2_rn(x, y);
    return *(uint32_t*)&h;
}

__global__ void __launch_bounds__(256, 2) flash_f16_kernel(
    const __half* __restrict__ qkv, __half* __restrict__ y)
{
    extern __shared__ __half fsm[];
    __half* qs = fsm;                       // 128 x 136

    const int tid = threadIdx.x;
    const int w = tid >> 5;
    const int l = tid & 31;
    const int lq = l >> 2;
    const int lr = l & 3;
    const int qt = gridDim.x - 1 - blockIdx.x;   // heavy tiles first
    const int h = blockIdx.y;
    const int b = blockIdx.z;
    const int q0 = qt * FBQ;

    const size_t rs = 3 * EMB;
    const __half* qb  = qkv + (size_t)(b * SEQ + q0) * rs + h * HEAD_DIM;
    const __half* kb0 = qkv + (size_t)(b * SEQ) * rs + EMB + h * HEAD_DIM;
    const __half* vb0 = kb0 + EMB;

    const uint32_t fsmu = smem_u32(fsm);
    const uint32_t qsu = fsmu;
    const uint32_t ksu0 = fsmu + (uint32_t)QS_HALVES * 2;
    const uint32_t vsu0 = ksu0 + (uint32_t)KV_HALVES * 2;

    const uint32_t qbase = qsu + (uint32_t)(((w * 16 + (l & 15)) * QST + ((l >> 4) << 3)) * 2);
    const uint32_t kbase0 = ksu0 + (uint32_t)(((((l & 7) + ((l >> 4) << 3)) * QST) + (((l >> 3) & 1) << 3)) * 2);
    const uint32_t vbase0 = vsu0 + (uint32_t)((((l & 15) * QST) + ((l >> 4) << 3)) * 2);

    const int lrow = tid >> 4, lcol = tid & 15;   // K/V tile loading coords

    auto load_kv = [&](int buf, int kt) {
        const __half* kb = kb0 + (size_t)kt * FBK * rs;
        const __half* vb = vb0 + (size_t)kt * FBK * rs;
        uint32_t kdst = ksu0 + (uint32_t)(buf * KVSTG) * 2;
        uint32_t vdst = kdst + (uint32_t)KV_HALVES * 2;
#pragma unroll
        for (int i = 0; i < 4; i++) {
            int row = lrow + i * 16;
            uint32_t soff = (uint32_t)(row * QST + lcol * 8) * 2;
            CP_ASYNC16(kdst + soff, kb + (size_t)row * rs + lcol * 8);
            CP_ASYNC16(vdst + soff, vb + (size_t)row * rs + lcol * 8);
        }
        CP_COMMIT();
    };

    // stage Q (plain stores): 128 rows x 16 chunks of 8 halves
#pragma unroll
    for (int i = 0; i < 8; i++) {
        int idx = tid + i * 256;
        int row = idx >> 4, c = idx & 15;
        *(uint4*)&qs[row * QST + c * 8] = *(const uint4*)(qb + (size_t)row * rs + c * 8);
    }

    float d[16][4];
#pragma unroll
    for (int nt = 0; nt < 16; nt++)
#pragma unroll
        for (int c = 0; c < 4; c++)
            d[nt][c] = 0.0f;

    float m0 = -INFINITY, m1 = -INFINITY, l0 = 0.0f, l1 = 0.0f;
    const float sc = 0.08838834764831845f;  // 1/sqrt(128)
    const int ktmax = 2 * qt + 1;
    const int myrowmax = q0 + w * 16 + 15;
    const int arow = w * 16 + lq;

    load_kv(0, 0);

    for (int kt = 0; kt <= ktmax; kt++) {
        const int buf = kt & 1;
        CP_WAIT0();
        __syncthreads();   // tile kt visible; prev-buffer compute retired; Q staged
        if (kt < ktmax) load_kv(buf ^ 1, kt + 1);

        const uint32_t kvoff = (uint32_t)(buf * KVSTG) * 2;
        const uint32_t kbase = kbase0 + kvoff;
        const uint32_t vbase = vbase0 + kvoff;

        const bool active = (kt * FBK <= myrowmax);
        if (active) {
            // ---- S = Q @ K^T ----
            float s[8][4];
#pragma unroll
            for (int nt = 0; nt < 8; nt++)
#pragma unroll
                for (int c = 0; c < 4; c++)
                    s[nt][c] = 0.0f;

#pragma unroll
            for (int k = 0; k < 8; k++) {
                uint32_t a0, a1, a2, a3;
                LDSM_X4(a0, a1, a2, a3, qbase + k * 32);
#pragma unroll
                for (int ntp = 0; ntp < 4; ntp++) {
                    uint32_t b0, b1, b2, b3;
                    LDSM_X4(b0, b1, b2, b3, kbase + (uint32_t)(ntp * 16 * QST * 2) + k * 32);
                    mma_f16(s[2 * ntp],     a0, a1, a2, a3, b0, b1);
                    mma_f16(s[2 * ntp + 1], a0, a1, a2, a3, b2, b3);
                }
            }

            // ---- scale + causal mask ----
            const bool domask = (kt >= 2 * qt);
#pragma unroll
            for (int nt = 0; nt < 8; nt++)
#pragma unroll
                for (int c = 0; c < 4; c++) {
                    float v = s[nt][c] * sc;
                    if (domask) {
                        int kg = kt * FBK + nt * 8 + 2 * lr + (c & 1);
                        int rg = q0 + arow + ((c >= 2) ? 8 : 0);
                        if (kg > rg) v = -INFINITY;
                    }
                    s[nt][c] = v;
                }

            // ---- online softmax (rows arow, arow+8) ----
            float mx0 = -INFINITY, mx1 = -INFINITY;
#pragma unroll
            for (int nt = 0; nt < 8; nt++) {
                mx0 = fmaxf(mx0, fmaxf(s[nt][0], s[nt][1]));
                mx1 = fmaxf(mx1, fmaxf(s[nt][2], s[nt][3]));
            }
            mx0 = fmaxf(mx0, __shfl_xor_sync(0xffffffffu, mx0, 1));
            mx0 = fmaxf(mx0, __shfl_xor_sync(0xffffffffu, mx0, 2));
            mx1 = fmaxf(mx1, __shfl_xor_sync(0xffffffffu, mx1, 1));
            mx1 = fmaxf(mx1, __shfl_xor_sync(0xffffffffu, mx1, 2));

            float nm0 = fmaxf(m0, mx0), nm1 = fmaxf(m1, mx1);
            float al0 = __expf(m0 - nm0), al1 = __expf(m1 - nm1);
            m0 = nm0; m1 = nm1;

            float sum0 = 0.0f, sum1 = 0.0f;
#pragma unroll
            for (int nt = 0; nt < 8; nt++) {
                float p0 = __expf(s[nt][0] - nm0);
                float p1 = __expf(s[nt][1] - nm0);
                float p2 = __expf(s[nt][2] - nm1);
                float p3 = __expf(s[nt][3] - nm1);
                s[nt][0] = p0; s[nt][1] = p1; s[nt][2] = p2; s[nt][3] = p3;
                sum0 += p0 + p1; sum1 += p2 + p3;
            }
            sum0 += __shfl_xor_sync(0xffffffffu, sum0, 1);
            sum0 += __shfl_xor_sync(0xffffffffu, sum0, 2);
            sum1 += __shfl_xor_sync(0xffffffffu, sum1, 1);
            sum1 += __shfl_xor_sync(0xffffffffu, sum1, 2);
            l0 = l0 * al0 + sum0;
            l1 = l1 * al1 + sum1;

#pragma unroll
            for (int nt = 0; nt < 16; nt++) {
                d[nt][0] *= al0; d[nt][1] *= al0;
                d[nt][2] *= al1; d[nt][3] *= al1;
            }

            // ---- O += P @ V (P fragments live in s[] registers) ----
#pragma unroll
            for (int kbk = 0; kbk < 4; kbk++) {
                uint32_t a0 = packh2(s[2 * kbk][0],     s[2 * kbk][1]);
                uint32_t a1 = packh2(s[2 * kbk][2],     s[2 * kbk][3]);
                uint32_t a2 = packh2(s[2 * kbk + 1][0], s[2 * kbk + 1][1]);
                uint32_t a3 = packh2(s[2 * kbk + 1][2], s[2 * kbk + 1][3]);
#pragma unroll
                for (int ntp = 0; ntp < 8; ntp++) {
                    uint32_t b0, b1, b2, b3;
                    LDSM_X4_T(b0, b1, b2, b3,
                              vbase + (uint32_t)(kbk * 16 * QST * 2) + ntp * 32);
                    mma_f16(d[2 * ntp],     a0, a1, a2, a3, b0, b1);
                    mma_f16(d[2 * ntp + 1], a0, a1, a2, a3, b2, b3);
                }
            }
        }
    }

    // epilogue: divide by l, write fp16 y
    float inv0 = 1.0f / l0, inv1 = 1.0f / l1;
    __half* yb  = y + (size_t)(b * SEQ + q0 + arow) * EMB + h * HEAD_DIM;
    __half* yb2 = yb + (size_t)8 * EMB;
#pragma unroll
    for (int nt = 0; nt < 16; nt++) {
        __half2 o0 = __floats2half2_rn(d[nt][0] * inv0, d[nt][1] * inv0);
        __half2 o1 = __floats2half2_rn(d[nt][2] * inv1, d[nt][3] * inv1);
        *(__half2*)&yb[nt * 8 + 2 * lr]  = o0;
        *(__half2*)&yb2[nt * 8 + 2 * lr] = o1;
    }
}

// ---------------------------------------------------------------------------
// Launch
// ---------------------------------------------------------------------------
extern "C" void kernel_launch(void* const* d_in, const int* in_sizes, int n_in,
                              void* d_out, int out_size)
{
    const float* x       = (const float*)d_in[0];
    const float* w_atten = (const float*)d_in[1];
    const float* w_proj  = (const float*)d_in[2];
    const float* fcos    = (const float*)d_in[3];
    const float* fsin    = (const float*)d_in[4];
    float* out = (float*)d_out;

    __half *qkv16 = nullptr, *y16 = nullptr, *a16 = nullptr, *b16 = nullptr;
    cudaGetSymbolAddress((void**)&qkv16, g_qkv16);
    cudaGetSymbolAddress((void**)&y16, g_y16);
    cudaGetSymbolAddress((void**)&a16, g_a16);
    cudaGetSymbolAddress((void**)&b16, g_b16);

    cudaFuncSetAttribute(gemm_f16_kernel<0>, cudaFuncAttributeMaxDynamicSharedMemorySize,
                         GEMM_SMEM);
    cudaFuncSetAttribute(gemm_f16_kernel<1>, cudaFuncAttributeMaxDynamicSharedMemorySize,
                         GEMM_SMEM);
    cudaFuncSetAttribute(flash_f16_kernel, cudaFuncAttributeMaxDynamicSharedMemorySize,
                         FLASH_SMEM);

    const int MROWS = BATCH * SEQ;                    // 4096
    const size_t NE = (size_t)MROWS * EMB;            // 16.7M
    const size_t NW1 = (size_t)EMB * 3 * EMB;         // 50.3M

    // 1) convert x and w_atten to fp16
    cvt16_kernel<<<(int)(NE / 2048), 256>>>(x, a16);
    cvt16_kernel<<<(int)(NW1 / 2048), 256>>>(w_atten, b16);

    // 2) qkv16 = rope(x @ w_atten) — fused epilogue
    {
        dim3 grid((3 * EMB) / BN, MROWS / BM);
        gemm_f16_kernel<0><<<grid, 256, GEMM_SMEM>>>(a16, b16, qkv16, fcos, fsin,
                                                     MROWS, 3 * EMB, EMB);
    }

    // 3) flash attention -> y16 (heavy tiles first)
    {
        dim3 grid(SEQ / FBQ, NUM_HEADS, BATCH);
        flash_f16_kernel<<<grid, 256, FLASH_SMEM>>>(qkv16, y16);
    }

    // 4) convert w_proj, then out = y @ w_proj (fp32 out)
    cvt16_kernel<<<(int)(NE / 2048), 256>>>(w_proj, b16);
    {
        dim3 grid(EMB / BN, MROWS / BM);
        gemm_f16_kernel<1><<<grid, 256, GEMM_SMEM>>>(y16, b16, out, nullptr, nullptr,
                                                     MROWS, EMB, EMB);
    }
}

// round 13
// speedup vs baseline: 1.0309x; 1.0014x over previous
#include <cuda_runtime.h>
#include <cuda_fp16.h>
#include <mma.h>
#include <math.h>
#include <stdint.h>

using namespace nvcuda;

#define NUM_HEADS 32
#define EMB 4096
#define HEAD_DIM 128
#define BATCH 2
#define SEQ 2048

// ---------------------------------------------------------------------------
// Scratch (no allocations allowed) — all fp16 activations
// ---------------------------------------------------------------------------
__device__ __half g_qkv16[(size_t)BATCH * SEQ * 3 * EMB];  // 100 MB
__device__ __half g_y16[(size_t)BATCH * SEQ * EMB];        // 33.5 MB
__device__ __half g_a16[(size_t)BATCH * SEQ * EMB];        // 33.5 MB (x fp16)
__device__ __half g_b16[(size_t)3 * EMB * EMB];            // 100 MB (w_atten fp16)
__device__ __half g_bp16[(size_t)EMB * EMB];               // 33.5 MB (w_proj fp16)

__device__ __forceinline__ uint32_t smem_u32(const void* p) {
    uint32_t a;
    asm("{ .reg .u64 t; cvta.to.shared.u64 t, %1; cvt.u32.u64 %0, t; }"
        : "=r"(a) : "l"(p));
    return a;
}

#define CP_ASYNC16(saddr, gptr) \
    asm volatile("cp.async.cg.shared.global [%0], [%1], 16;" \
        :: "r"(saddr), "l"(gptr))
#define CP_COMMIT() asm volatile("cp.async.commit_group;")
#define CP_WAIT1()  asm volatile("cp.async.wait_group 1;")
#define CP_WAIT0()  asm volatile("cp.async.wait_group 0;")

#define LDSM_X4(r0, r1, r2, r3, addr) \
    asm volatile("ldmatrix.sync.aligned.m8n8.x4.shared.b16 {%0,%1,%2,%3}, [%4];" \
        : "=r"(r0), "=r"(r1), "=r"(r2), "=r"(r3) : "r"(addr))
#define LDSM_X4_T(r0, r1, r2, r3, addr) \
    asm volatile("ldmatrix.sync.aligned.m8n8.x4.trans.shared.b16 {%0,%1,%2,%3}, [%4];" \
        : "=r"(r0), "=r"(r1), "=r"(r2), "=r"(r3) : "r"(addr))

// ---------------------------------------------------------------------------
// fp32 -> fp16 conversion, 8 elements per thread
// ---------------------------------------------------------------------------
__global__ void __launch_bounds__(256) cvt16_kernel(
    const float* __restrict__ in, __half* __restrict__ out)
{
    size_t i = ((size_t)blockIdx.x * 256 + threadIdx.x) * 8;
    float4 v0 = *(const float4*)(in + i);
    float4 v1 = *(const float4*)(in + i + 4);
    __half2 h[4];
    h[0] = __floats2half2_rn(v0.x, v0.y);
    h[1] = __floats2half2_rn(v0.z, v0.w);
    h[2] = __floats2half2_rn(v1.x, v1.y);
    h[3] = __floats2half2_rn(v1.z, v1.w);
    *(uint4*)(out + i) = *(uint4*)h;
}

// ---------------------------------------------------------------------------
// fp16 WMMA GEMM — R6 config (measured best): cp.async 3-stage pipeline,
// 256 threads, 8 warps as 2(M)x4(N), warp tile 64x32. Block 128x128, K-step 32.
// MODE 0: output fp16 with fused RoPE (cols < 2*EMB). MODE 1: fp32 plain.
// ---------------------------------------------------------------------------
#define BM 128
#define BN 128
#define BK 32
#define AST 40
#define BST 136
#define ATILE (BM * AST)      // 5120 halves
#define BTILE (BK * BST)      // 4352 halves
#define STG (ATILE + BTILE)   // 9472 halves per stage
#define NSTAGE 3
#define GEMM_SMEM (STG * NSTAGE * 2)   // 56832 bytes

template <int MODE>
__global__ void __launch_bounds__(256, 2) gemm_f16_kernel(
    const __half* __restrict__ A, const __half* __restrict__ B,
    void* __restrict__ Cv,
    const float* __restrict__ fcos, const float* __restrict__ fsin,
    int M, int N, int K)
{
    extern __shared__ __half hsm[];
    const uint32_t smb = smem_u32(hsm);

    const int tid = threadIdx.x;
    const int wid = tid >> 5;
    const int l = tid & 31;
    const int wM = wid >> 2;   // 0..1
    const int wN = wid & 3;    // 0..3
    const int bm = blockIdx.y * BM;
    const int bn = blockIdx.x * BN;

    wmma::fragment<wmma::accumulator, 16, 16, 16, float> cf[4][2];
#pragma unroll
    for (int i = 0; i < 4; i++)
#pragma unroll
        for (int j = 0; j < 2; j++)
            wmma::fill_fragment(cf[i][j], 0.0f);

    const int ar = tid >> 2, ac = tid & 3;
    const int br = tid >> 4, bc = tid & 15;

    auto load_stage = [&](int s, int k0) {
        uint32_t abase = smb + (uint32_t)(s * STG) * 2;
        uint32_t bbase = abase + (uint32_t)ATILE * 2;
#pragma unroll
        for (int it = 0; it < 2; it++) {
            CP_ASYNC16(abase + (uint32_t)((ar + it * 64) * AST + ac * 8) * 2,
                       A + (size_t)(bm + ar + it * 64) * K + k0 + ac * 8);
            CP_ASYNC16(bbase + (uint32_t)((br + it * 16) * BST + bc * 8) * 2,
                       B + (size_t)(k0 + br + it * 16) * N + bn + bc * 8);
        }
        CP_COMMIT();
    };

    load_stage(0, 0);
    load_stage(1, BK);

    int st = 0;
    for (int k0 = 0; k0 < K; k0 += BK) {
        CP_WAIT1();
        __syncthreads();
        const __half* As = hsm + st * STG;
        const __half* Bs = As + ATILE;
#pragma unroll
        for (int kk = 0; kk < BK; kk += 16) {
            wmma::fragment<wmma::matrix_a, 16, 16, 16, __half, wmma::row_major> af[4];
            wmma::fragment<wmma::matrix_b, 16, 16, 16, __half, wmma::row_major> bf[2];
#pragma unroll
            for (int i = 0; i < 4; i++)
                wmma::load_matrix_sync(af[i], &As[(wM * 64 + i * 16) * AST + kk], AST);
#pragma unroll
            for (int j = 0; j < 2; j++)
                wmma::load_matrix_sync(bf[j], &Bs[kk * BST + wN * 32 + j * 16], BST);
#pragma unroll
            for (int i = 0; i < 4; i++)
#pragma unroll
                for (int j = 0; j < 2; j++)
                    wmma::mma_sync(cf[i][j], af[i], bf[j], cf[i][j]);
        }
        int kn = k0 + 2 * BK;
        if (kn < K) load_stage(st == 0 ? 2 : st - 1, kn);  // (st+2)%3
        else        CP_COMMIT();   // empty group keeps one-group-per-iter invariant
        st = (st == 2) ? 0 : st + 1;
        __syncthreads();
    }
    CP_WAIT0();
    __syncthreads();

    if (MODE == 1) {
        float* C = (float*)Cv;
#pragma unroll
        for (int i = 0; i < 4; i++)
#pragma unroll
            for (int j = 0; j < 2; j++) {
                size_t row = (size_t)bm + wM * 64 + i * 16;
                size_t col = (size_t)bn + wN * 32 + j * 16;
                wmma::store_matrix_sync(C + row * N + col, cf[i][j], N, wmma::mem_row_major);
            }
    } else {
        __half* C = (__half*)Cv;
        float* stage = (float*)hsm + wid * 320;
        const bool doRope = (bn < 2 * EMB);
        const int row_l = l >> 1;
        const int ch = (l & 1) * 8;
#pragma unroll
        for (int i = 0; i < 4; i++)
#pragma unroll
            for (int j = 0; j < 2; j++) {
                wmma::store_matrix_sync(stage, cf[i][j], 20, wmma::mem_row_major);
                __syncwarp();
                const float* sp = stage + row_l * 20 + ch;
                int grow = bm + wM * 64 + i * 16 + row_l;
                int gcol = bn + wN * 32 + j * 16 + ch;
                __half hbuf[8];
                if (doRope) {
                    int sidx = grow & (SEQ - 1);
                    int d2b = (gcol & 127) >> 1;
#pragma unroll
                    for (int t = 0; t < 4; t++) {
                        float c = fcos[sidx * 64 + d2b + t];
                        float sn = fsin[sidx * 64 + d2b + t];
                        float xr = sp[2 * t], xi = sp[2 * t + 1];
                        hbuf[2 * t]     = __float2half(xr * c - xi * sn);
                        hbuf[2 * t + 1] = __float2half(xr * sn + xi * c);
                    }
                } else {
#pragma unroll
                    for (int t = 0; t < 8; t++)
                        hbuf[t] = __float2half(sp[t]);
                }
                *(uint4*)(C + (size_t)grow * N + gcol) = *(uint4*)hbuf;
                __syncwarp();
            }
    }
}

// ---------------------------------------------------------------------------
// Flash attention, fp16 mma.sync m16n8k16, causal, online softmax.
// cp.async double-buffered K/V (R9 measured-best loop shape);
// ldmatrix.x4 fragments; P in registers. Heavy q-tiles scheduled first.
// ---------------------------------------------------------------------------
#define FBQ 128
#define FBK 64
#define QST 136
#define QS_HALVES (FBQ * QST)
#define KV_HALVES (FBK * QST)
#define KVSTG (2 * KV_HALVES)
#define FLASH_SMEM ((QS_HALVES + 2 * KVSTG) * 2)   // 104448 bytes

__device__ __forceinline__ void mma_f16(float* d,
    uint32_t a0, uint32_t a1, uint32_t a2, uint32_t a3,
    uint32_t b0, uint32_t b1)
{
    asm volatile(
        "mma.sync.aligned.m16n8k16.row.col.f32.f16.f16.f32 "
        "{%0,%1,%2,%3},{%4,%5,%6,%7},{%8,%9},{%0,%1,%2,%3};\n"
        : "+f"(d[0]), "+f"(d[1]), "+f"(d[2]), "+f"(d[3])
        : "r"(a0), "r"(a1), "r"(a2), "r"(a3), "r"(b0), "r"(b1));
}

__device__ __forceinline__ uint32_t packh2(float x, float y) {
    __half2 h = __floats2half2_rn(x, y);
    return *(uint32_t*)&h;
}

__global__ void __launch_bounds__(256, 2) flash_f16_kernel(
    const __half* __restrict__ qkv, __half* __restrict__ y)
{
    extern __shared__ __half fsm[];
    __half* qs = fsm;

    const int tid = threadIdx.x;
    const int w = tid >> 5;
    const int l = tid & 31;
    const int lq = l >> 2;
    const int lr = l & 3;
    const int qt = gridDim.x - 1 - blockIdx.x;   // heavy tiles first
    const int h = blockIdx.y;
    const int b = blockIdx.z;
    const int q0 = qt * FBQ;

    const size_t rs = 3 * EMB;
    const __half* qb  = qkv + (size_t)(b * SEQ + q0) * rs + h * HEAD_DIM;
    const __half* kb0 = qkv + (size_t)(b * SEQ) * rs + EMB + h * HEAD_DIM;
    const __half* vb0 = kb0 + EMB;

    const uint32_t fsmu = smem_u32(fsm);
    const uint32_t qsu = fsmu;
    const uint32_t ksu0 = fsmu + (uint32_t)QS_HALVES * 2;
    const uint32_t vsu0 = ksu0 + (uint32_t)KV_HALVES * 2;

    const uint32_t qbase = qsu + (uint32_t)(((w * 16 + (l & 15)) * QST + ((l >> 4) << 3)) * 2);
    const uint32_t kbase0 = ksu0 + (uint32_t)(((((l & 7) + ((l >> 4) << 3)) * QST) + (((l >> 3) & 1) << 3)) * 2);
    const uint32_t vbase0 = vsu0 + (uint32_t)((((l & 15) * QST) + ((l >> 4) << 3)) * 2);

    const int lrow = tid >> 4, lcol = tid & 15;

    auto load_kv = [&](int buf, int kt) {
        const __half* kb = kb0 + (size_t)kt * FBK * rs;
        const __half* vb = vb0 + (size_t)kt * FBK * rs;
        uint32_t kdst = ksu0 + (uint32_t)(buf * KVSTG) * 2;
        uint32_t vdst = kdst + (uint32_t)KV_HALVES * 2;
#pragma unroll
        for (int i = 0; i < 4; i++) {
            int row = lrow + i * 16;
            uint32_t soff = (uint32_t)(row * QST + lcol * 8) * 2;
            CP_ASYNC16(kdst + soff, kb + (size_t)row * rs + lcol * 8);
            CP_ASYNC16(vdst + soff, vb + (size_t)row * rs + lcol * 8);
        }
        CP_COMMIT();
    };

#pragma unroll
    for (int i = 0; i < 8; i++) {
        int idx = tid + i * 256;
        int row = idx >> 4, c = idx & 15;
        *(uint4*)&qs[row * QST + c * 8] = *(const uint4*)(qb + (size_t)row * rs + c * 8);
    }

    float d[16][4];
#pragma unroll
    for (int nt = 0; nt < 16; nt++)
#pragma unroll
        for (int c = 0; c < 4; c++)
            d[nt][c] = 0.0f;

    float m0 = -INFINITY, m1 = -INFINITY, l0 = 0.0f, l1 = 0.0f;
    const float sc = 0.08838834764831845f;
    const int ktmax = 2 * qt + 1;
    const int myrowmax = q0 + w * 16 + 15;
    const int arow = w * 16 + lq;

    load_kv(0, 0);

    for (int kt = 0; kt <= ktmax; kt++) {
        const int buf = kt & 1;
        if (kt < ktmax) { load_kv(buf ^ 1, kt + 1); CP_WAIT1(); }
        else           { CP_WAIT0(); }
        __syncthreads();

        const uint32_t kvoff = (uint32_t)(buf * KVSTG) * 2;
        const uint32_t kbase = kbase0 + kvoff;
        const uint32_t vbase = vbase0 + kvoff;

        const bool active = (kt * FBK <= myrowmax);
        if (active) {
            float s[8][4];
#pragma unroll
            for (int nt = 0; nt < 8; nt++)
#pragma unroll
                for (int c = 0; c < 4; c++)
                    s[nt][c] = 0.0f;

#pragma unroll
            for (int k = 0; k < 8; k++) {
                uint32_t a0, a1, a2, a3;
                LDSM_X4(a0, a1, a2, a3, qbase + k * 32);
#pragma unroll
                for (int ntp = 0; ntp < 4; ntp++) {
                    uint32_t b0, b1, b2, b3;
                    LDSM_X4(b0, b1, b2, b3, kbase + (uint32_t)(ntp * 16 * QST * 2) + k * 32);
                    mma_f16(s[2 * ntp],     a0, a1, a2, a3, b0, b1);
                    mma_f16(s[2 * ntp + 1], a0, a1, a2, a3, b2, b3);
                }
            }

            const bool domask = (kt >= 2 * qt);
#pragma unroll
            for (int nt = 0; nt < 8; nt++)
#pragma unroll
                for (int c = 0; c < 4; c++) {
                    float v = s[nt][c] * sc;
                    if (domask) {
                        int kg = kt * FBK + nt * 8 + 2 * lr + (c & 1);
                        int rg = q0 + arow + ((c >= 2) ? 8 : 0);
                        if (kg > rg) v = -INFINITY;
                    }
                    s[nt][c] = v;
                }

            float mx0 = -INFINITY, mx1 = -INFINITY;
#pragma unroll
            for (int nt = 0; nt < 8; nt++) {
                mx0 = fmaxf(mx0, fmaxf(s[nt][0], s[nt][1]));
                mx1 = fmaxf(mx1, fmaxf(s[nt][2], s[nt][3]));
            }
            mx0 = fmaxf(mx0, __shfl_xor_sync(0xffffffffu, mx0, 1));
            mx0 = fmaxf(mx0, __shfl_xor_sync(0xffffffffu, mx0, 2));
            mx1 = fmaxf(mx1, __shfl_xor_sync(0xffffffffu, mx1, 1));
            mx1 = fmaxf(mx1, __shfl_xor_sync(0xffffffffu, mx1, 2));

            float nm0 = fmaxf(m0, mx0), nm1 = fmaxf(m1, mx1);
            float al0 = __expf(m0 - nm0), al1 = __expf(m1 - nm1);
            m0 = nm0; m1 = nm1;

            float sum0 = 0.0f, sum1 = 0.0f;
#pragma unroll
            for (int nt = 0; nt < 8; nt++) {
                float p0 = __expf(s[nt][0] - nm0);
                float p1 = __expf(s[nt][1] - nm0);
                float p2 = __expf(s[nt][2] - nm1);
                float p3 = __expf(s[nt][3] - nm1);
                s[nt][0] = p0; s[nt][1] = p1; s[nt][2] = p2; s[nt][3] = p3;
                sum0 += p0 + p1; sum1 += p2 + p3;
            }
            sum0 += __shfl_xor_sync(0xffffffffu, sum0, 1);
            sum0 += __shfl_xor_sync(0xffffffffu, sum0, 2);
            sum1 += __shfl_xor_sync(0xffffffffu, sum1, 1);
            sum1 += __shfl_xor_sync(0xffffffffu, sum1, 2);
            l0 = l0 * al0 + sum0;
            l1 = l1 * al1 + sum1;

#pragma unroll
            for (int nt = 0; nt < 16; nt++) {
                d[nt][0] *= al0; d[nt][1] *= al0;
                d[nt][2] *= al1; d[nt][3] *= al1;
            }

#pragma unroll
            for (int kbk = 0; kbk < 4; kbk++) {
                uint32_t a0 = packh2(s[2 * kbk][0],     s[2 * kbk][1]);
                uint32_t a1 = packh2(s[2 * kbk][2],     s[2 * kbk][3]);
                uint32_t a2 = packh2(s[2 * kbk + 1][0], s[2 * kbk + 1][1]);
                uint32_t a3 = packh2(s[2 * kbk + 1][2], s[2 * kbk + 1][3]);
#pragma unroll
                for (int ntp = 0; ntp < 8; ntp++) {
                    uint32_t b0, b1, b2, b3;
                    LDSM_X4_T(b0, b1, b2, b3,
                              vbase + (uint32_t)(kbk * 16 * QST * 2) + ntp * 32);
                    mma_f16(d[2 * ntp],     a0, a1, a2, a3, b0, b1);
                    mma_f16(d[2 * ntp + 1], a0, a1, a2, a3, b2, b3);
                }
            }
        }
        __syncthreads();
    }

    float inv0 = 1.0f / l0, inv1 = 1.0f / l1;
    __half* yb  = y + (size_t)(b * SEQ + q0 + arow) * EMB + h * HEAD_DIM;
    __half* yb2 = yb + (size_t)8 * EMB;
#pragma unroll
    for (int nt = 0; nt < 16; nt++) {
        __half2 o0 = __floats2half2_rn(d[nt][0] * inv0, d[nt][1] * inv0);
        __half2 o1 = __floats2half2_rn(d[nt][2] * inv1, d[nt][3] * inv1);
        *(__half2*)&yb[nt * 8 + 2 * lr]  = o0;
        *(__half2*)&yb2[nt * 8 + 2 * lr] = o1;
    }
}

// ---------------------------------------------------------------------------
// Launch — side stream overlaps weight conversion with GEMM1/flash.
// Stream + events created once on first (uncaptured) correctness call;
// during graph capture the event fork/join is the canonical multi-stream
// capture pattern.
// ---------------------------------------------------------------------------
extern "C" void kernel_launch(void* const* d_in, const int* in_sizes, int n_in,
                              void* d_out, int out_size)
{
    const float* x       = (const float*)d_in[0];
    const float* w_atten = (const float*)d_in[1];
    const float* w_proj  = (const float*)d_in[2];
    const float* fcos    = (const float*)d_in[3];
    const float* fsin    = (const float*)d_in[4];
    float* out = (float*)d_out;

    __half *qkv16 = nullptr, *y16 = nullptr, *a16 = nullptr, *b16 = nullptr, *bp16 = nullptr;
    cudaGetSymbolAddress((void**)&qkv16, g_qkv16);
    cudaGetSymbolAddress((void**)&y16, g_y16);
    cudaGetSymbolAddress((void**)&a16, g_a16);
    cudaGetSymbolAddress((void**)&b16, g_b16);
    cudaGetSymbolAddress((void**)&bp16, g_bp16);

    static cudaStream_t s2 = nullptr;
    static cudaEvent_t ev_fork = nullptr, ev_wa = nullptr, ev_wp = nullptr;
    if (s2 == nullptr) {
        cudaStreamCreateWithFlags(&s2, cudaStreamNonBlocking);
        cudaEventCreateWithFlags(&ev_fork, cudaEventDisableTiming);
        cudaEventCreateWithFlags(&ev_wa, cudaEventDisableTiming);
        cudaEventCreateWithFlags(&ev_wp, cudaEventDisableTiming);
        cudaFuncSetAttribute(gemm_f16_kernel<0>,
                             cudaFuncAttributeMaxDynamicSharedMemorySize, GEMM_SMEM);
        cudaFuncSetAttribute(gemm_f16_kernel<1>,
                             cudaFuncAttributeMaxDynamicSharedMemorySize, GEMM_SMEM);
        cudaFuncSetAttribute(flash_f16_kernel,
                             cudaFuncAttributeMaxDynamicSharedMemorySize, FLASH_SMEM);
    }

    const int MROWS = BATCH * SEQ;                    // 4096
    const size_t NE = (size_t)MROWS * EMB;            // 16.7M
    const size_t NW1 = (size_t)EMB * 3 * EMB;         // 50.3M

    // fork side stream
    cudaEventRecord(ev_fork, 0);
    cudaStreamWaitEvent(s2, ev_fork, 0);

    // s2: convert both weight matrices (w_atten needed by GEMM1; w_proj later)
    cvt16_kernel<<<(int)(NW1 / 2048), 256, 0, s2>>>(w_atten, b16);
    cudaEventRecord(ev_wa, s2);
    cvt16_kernel<<<(int)(NE / 2048), 256, 0, s2>>>(w_proj, bp16);
    cudaEventRecord(ev_wp, s2);

    // main stream: convert x concurrently
    cvt16_kernel<<<(int)(NE / 2048), 256>>>(x, a16);

    // GEMM1 waits for w_atten conversion
    cudaStreamWaitEvent(0, ev_wa, 0);
    {
        dim3 grid((3 * EMB) / BN, MROWS / BM);
        gemm_f16_kernel<0><<<grid, 256, GEMM_SMEM>>>(a16, b16, qkv16, fcos, fsin,
                                                     MROWS, 3 * EMB, EMB);
    }

    // flash attention -> y16 (w_proj conversion still running on s2 underneath)
    {
        dim3 grid(SEQ / FBQ, NUM_HEADS, BATCH);
        flash_f16_kernel<<<grid, 256, FLASH_SMEM>>>(qkv16, y16);
    }

    // GEMM2 waits for w_proj conversion (joins s2 into main stream)
    cudaStreamWaitEvent(0, ev_wp, 0);
    {
        dim3 grid(EMB / BN, MROWS / BM);
        gemm_f16_kernel<1><<<grid, 256, GEMM_SMEM>>>(y16, bp16, out, nullptr, nullptr,
                                                     MROWS, EMB, EMB);
    }
}